// round 14
// baseline (speedup 1.0000x reference)
#include <cuda_runtime.h>
#include <cuda_bf16.h>
#include <cstdint>

#define BH 64
#define SEQ 8192
#define D 64
#define SPLITS 16
#define RPS (SEQ / SPLITS)      // 512
#define K1CH 32
#define K1NCH (RPS / K1CH)      // 16
#define PART_STRIDE (D * D + D)

__device__ float g_part[BH * SPLITS * PART_STRIDE];
__device__ float g_ctx[BH * D * D];

__device__ __forceinline__ uint32_t tf32r(float x) {
    uint32_t r;
    asm("cvt.rna.tf32.f32 %0, %1;" : "=r"(r) : "f"(x));
    return r;
}
__device__ __forceinline__ void mma_tf32(float* c, const uint32_t* a,
                                         uint32_t b0, uint32_t b1) {
    asm volatile(
        "mma.sync.aligned.m16n8k8.row.col.f32.tf32.tf32.f32 "
        "{%0,%1,%2,%3}, {%4,%5,%6,%7}, {%8,%9}, {%0,%1,%2,%3};"
        : "+f"(c[0]), "+f"(c[1]), "+f"(c[2]), "+f"(c[3])
        : "r"(a[0]), "r"(a[1]), "r"(a[2]), "r"(a[3]), "r"(b0), "r"(b1));
}
__device__ __forceinline__ uint32_t smem_u32(const void* p) {
    uint32_t a;
    asm("{ .reg .u64 t; cvta.to.shared.u64 t, %1; cvt.u32.u64 %0, t; }"
        : "=r"(a) : "l"(p));
    return a;
}
__device__ __forceinline__ void cpa16(uint32_t dst, const void* src) {
    asm volatile("cp.async.cg.shared.global [%0], [%1], 16;"
                 :: "r"(dst), "l"(src));
}
#define CPA_COMMIT() asm volatile("cp.async.commit_group;" ::: "memory")
#define CPA_WAIT(n) asm volatile("cp.async.wait_group %0;" :: "n"(n) : "memory")

// ============== Kernel 1: partial context  exp(K)^T @ V  (R12 best) =========
// grid (BH, SPLITS), 128 threads = 4 warps (2x2 tiling, warp tile M32xN32).
// Register staging (LDG->regs->exp/cvt->STS), double buffer, 1 barrier/chunk.
__global__ void __launch_bounds__(128) ctx_partial_kernel(
    const float* __restrict__ k, const float* __restrict__ v) {
    __shared__ __align__(16) uint32_t ek[2][K1CH * 72];  // 18 KB
    __shared__ __align__(16) uint32_t vv[2][K1CH * 72];  // 18 KB
    __shared__ float zred[8][64];

    const int head = blockIdx.x, split = blockIdx.y;
    const float* kb = k + (size_t)head * SEQ * D + (size_t)split * RPS * D;
    const float* vb = v + (size_t)head * SEQ * D + (size_t)split * RPS * D;

    const int tid = threadIdx.x;
    const int lane = tid & 31;
    const int wq = tid >> 5;
    const int g = lane >> 2, t4 = lane & 3;
    const int wm = wq & 1, wn = wq >> 1;
    const int sr = tid >> 4;
    const int c4 = (tid & 15) * 4;

    float acc[2][4][4];
#pragma unroll
    for (int i = 0; i < 2; i++)
#pragma unroll
        for (int j = 0; j < 4; j++)
#pragma unroll
            for (int l = 0; l < 4; l++) acc[i][j][l] = 0.0f;
    float zacc[4] = {0.0f, 0.0f, 0.0f, 0.0f};

    float4 kreg[4], vreg[4];

#define K1_LOAD(c)                                                           \
    {                                                                        \
        _Pragma("unroll") for (int s = 0; s < 4; s++) {                      \
            const int r = s * 8 + sr;                                        \
            kreg[s] = *(const float4*)&kb[(size_t)((c) * K1CH + r) * D + c4];\
            vreg[s] = *(const float4*)&vb[(size_t)((c) * K1CH + r) * D + c4];\
        }                                                                    \
    }

#define K1_STAGE(b)                                                          \
    do {                                                                     \
        _Pragma("unroll") for (int s = 0; s < 4; s++) {                      \
            const int r = s * 8 + sr;                                        \
            uint4 eu, vu;                                                    \
            eu.x = tf32r(__expf(kreg[s].x));                                 \
            eu.y = tf32r(__expf(kreg[s].y));                                 \
            eu.z = tf32r(__expf(kreg[s].z));                                 \
            eu.w = tf32r(__expf(kreg[s].w));                                 \
            zacc[0] += __uint_as_float(eu.x);                                \
            zacc[1] += __uint_as_float(eu.y);                                \
            zacc[2] += __uint_as_float(eu.z);                                \
            zacc[3] += __uint_as_float(eu.w);                                \
            vu.x = tf32r(vreg[s].x); vu.y = tf32r(vreg[s].y);                \
            vu.z = tf32r(vreg[s].z); vu.w = tf32r(vreg[s].w);                \
            *(uint4*)&ek[b][r * 72 + c4] = eu;                               \
            *(uint4*)&vv[b][r * 72 + c4] = vu;                               \
        }                                                                    \
    } while (0)

    K1_LOAD(0);
    K1_STAGE(0);
    __syncthreads();

    for (int c = 0; c < K1NCH; c++) {
        const int p = c & 1;
        if (c + 1 < K1NCH) K1_LOAD(c + 1);
#pragma unroll
        for (int ks = 0; ks < 4; ks++) {
            const int n0 = ks * 8;
            const int ra = (n0 + t4) * 72, rb = (n0 + 4 + t4) * 72;
            uint32_t A[2][4];
#pragma unroll
            for (int mt = 0; mt < 2; mt++) {
                const int dd = wm * 32 + mt * 16 + g;
                A[mt][0] = ek[p][ra + dd];
                A[mt][1] = ek[p][ra + dd + 8];
                A[mt][2] = ek[p][rb + dd];
                A[mt][3] = ek[p][rb + dd + 8];
            }
#pragma unroll
            for (int nt = 0; nt < 4; nt++) {
                const int ee = wn * 32 + nt * 8 + g;
                uint32_t b0 = vv[p][ra + ee];
                uint32_t b1 = vv[p][rb + ee];
                mma_tf32(acc[0][nt], A[0], b0, b1);
                mma_tf32(acc[1][nt], A[1], b0, b1);
            }
        }
        if (c + 1 < K1NCH) K1_STAGE(p ^ 1);
        __syncthreads();
    }

    float* np = g_part + (size_t)(head * SPLITS + split) * PART_STRIDE;
#pragma unroll
    for (int mt = 0; mt < 2; mt++) {
        const int d0 = wm * 32 + mt * 16 + g;
#pragma unroll
        for (int nt = 0; nt < 4; nt++) {
            const int ee = wn * 32 + nt * 8 + 2 * t4;
            *(float2*)&np[d0 * D + ee] =
                make_float2(acc[mt][nt][0], acc[mt][nt][1]);
            *(float2*)&np[(d0 + 8) * D + ee] =
                make_float2(acc[mt][nt][2], acc[mt][nt][3]);
        }
    }
#pragma unroll
    for (int j = 0; j < 4; j++) zred[sr][c4 + j] = zacc[j];
    __syncthreads();
    if (tid < 64) {
        float s = 0.0f;
#pragma unroll
        for (int t = 0; t < 8; t++) s += zred[t][tid];
        np[D * D + tid] = s;
    }
}

// ============== Kernel 2: reduce splits + normalize -> g_ctx ================
__global__ void __launch_bounds__(256) reduce_ctx_kernel() {
    const int head = blockIdx.x;
    const int tid = threadIdx.x;
    __shared__ float zs[D];
    const float* pb = g_part + (size_t)head * SPLITS * PART_STRIDE;

    if (tid < D) {
        float s = 0.0f;
#pragma unroll
        for (int sp = 0; sp < SPLITS; sp++) s += pb[sp * PART_STRIDE + D * D + tid];
        zs[tid] = 1.0f / s;
    }
    __syncthreads();

    const int i0 = blockIdx.y * 1024;
    for (int i = i0 + tid; i < i0 + 1024; i += 256) {
        float s = 0.0f;
#pragma unroll
        for (int sp = 0; sp < SPLITS; sp++) s += pb[sp * PART_STRIDE + i];
        g_ctx[head * D * D + i] = s * zs[i >> 6];
    }
}

// ============== Kernel 3: out = (softmax_ch(q)/8) @ ctx =====================
// grid (BH, 8), 256 threads = 8 warps (4x2 grid, warp tile M32xN32),
// 8 tiles of 128 rows. cp.async raw-q depth-2 ring; exp+tf32 at fragment
// time; row sums from A fragments.
#define QS_W 68
#define QS_WORDS (128 * QS_W)                 // 8704
#define K3_SMEM ((2 * QS_WORDS + 64 * 72 + 128) * 4)   // ~86.5 KB

__global__ void __launch_bounds__(256) out_kernel(
    const float* __restrict__ q, float* __restrict__ out) {
    extern __shared__ uint32_t sm3[];
    uint32_t* qs0 = sm3;
    uint32_t* qs1 = sm3 + QS_WORDS;
    uint32_t* ctxs = sm3 + 2 * QS_WORDS;      // 64*72
    float* ssum = (float*)(sm3 + 2 * QS_WORDS + 64 * 72);

    const int tid = threadIdx.x;
    const int lane = tid & 31;
    const int wq = tid >> 5;
    const int g = lane >> 2, t4 = lane & 3;
    const int wm = wq & 3, wn = wq >> 2;      // 4 x 2 warp grid
    const int sr = tid >> 4;                  // 0..15
    const int c4 = (tid & 15) * 4;
    const int head = blockIdx.x;

    const uint32_t uQs0 = smem_u32(qs0), uQs1 = smem_u32(qs1);

    // stage B = ctx (tf32-rounded), [d][e] rows, stride 72
    const float* gc = g_ctx + (size_t)head * D * D;
    for (int i = tid; i < 64 * 16; i += 256) {
        const int d = i >> 4, cg4 = (i & 15) * 4;
        float4 cv = *(const float4*)&gc[d * D + cg4];
        uint4 cu;
        cu.x = tf32r(cv.x); cu.y = tf32r(cv.y);
        cu.z = tf32r(cv.z); cu.w = tf32r(cv.w);
        *(uint4*)&ctxs[d * 72 + cg4] = cu;
    }

    const float* qh = q + (size_t)head * SEQ * D;
    const int tile0 = blockIdx.y * 8;         // units of 128 rows

    // prologue: tile 0 -> qs0 (128 rows x 64 cols, 8 cpa16/thread)
#pragma unroll
    for (int s = 0; s < 8; s++) {
        const int r = s * 16 + sr;
        cpa16(uQs0 + (r * QS_W + c4) * 4,
              &qh[(size_t)(tile0 * 128 + r) * D + c4]);
    }
    CPA_COMMIT();

    for (int t = 0; t < 8; t++) {
        const int p = t & 1;
        const int row0 = (tile0 + t) * 128;

        if (t + 1 < 8) {
            const uint32_t uDst = p ? uQs0 : uQs1;
#pragma unroll
            for (int s = 0; s < 8; s++) {
                const int r = s * 16 + sr;
                cpa16(uDst + (r * QS_W + c4) * 4,
                      &qh[(size_t)(row0 + 128 + r) * D + c4]);
            }
            CPA_COMMIT();
            CPA_WAIT(1);
        } else {
            CPA_WAIT(0);
        }
        __syncthreads();   // tile t visible

        const uint32_t* qsp = p ? qs1 : qs0;

        float acc[2][4][4];
#pragma unroll
        for (int i = 0; i < 2; i++)
#pragma unroll
            for (int j = 0; j < 4; j++)
#pragma unroll
                for (int l = 0; l < 4; l++) acc[i][j][l] = 0.0f;
        float asum[2][2] = {{0.0f, 0.0f}, {0.0f, 0.0f}};

#pragma unroll
        for (int ks = 0; ks < 8; ks++) {
            const int d0 = ks * 8;
            uint32_t A[2][4];
#pragma unroll
            for (int mt = 0; mt < 2; mt++) {
                const int rb = wm * 32 + mt * 16;
                const float x0 = __uint_as_float(qsp[(rb + g) * QS_W + d0 + t4]);
                const float x1 = __uint_as_float(qsp[(rb + 8 + g) * QS_W + d0 + t4]);
                const float x2 = __uint_as_float(qsp[(rb + g) * QS_W + d0 + 4 + t4]);
                const float x3 = __uint_as_float(qsp[(rb + 8 + g) * QS_W + d0 + 4 + t4]);
                A[mt][0] = tf32r(__expf(x0));
                A[mt][1] = tf32r(__expf(x1));
                A[mt][2] = tf32r(__expf(x2));
                A[mt][3] = tf32r(__expf(x3));
                asum[mt][0] += __uint_as_float(A[mt][0]) + __uint_as_float(A[mt][2]);
                asum[mt][1] += __uint_as_float(A[mt][1]) + __uint_as_float(A[mt][3]);
            }
            const int ra = (d0 + t4) * 72, rbb = (d0 + 4 + t4) * 72;
#pragma unroll
            for (int nt = 0; nt < 4; nt++) {
                const int ee = wn * 32 + nt * 8 + g;
                uint32_t b0 = ctxs[ra + ee];
                uint32_t b1 = ctxs[rbb + ee];
                mma_tf32(acc[0][nt], A[0], b0, b1);
                mma_tf32(acc[1][nt], A[1], b0, b1);
            }
        }

        // complete row sums over t4 lanes; wn==0 warps publish
#pragma unroll
        for (int mt = 0; mt < 2; mt++)
#pragma unroll
            for (int h = 0; h < 2; h++) {
                float v = asum[mt][h];
                v += __shfl_xor_sync(0xffffffffu, v, 1);
                v += __shfl_xor_sync(0xffffffffu, v, 2);
                asum[mt][h] = v;
            }
        if (wn == 0 && t4 == 0) {
#pragma unroll
            for (int mt = 0; mt < 2; mt++) {
                const int rb = wm * 32 + mt * 16;
                ssum[rb + g] = 0.125f / asum[mt][0];
                ssum[rb + 8 + g] = 0.125f / asum[mt][1];
            }
        }
        __syncthreads();   // ssum ready; qs[p] reads complete

        float* ob = out + (size_t)head * SEQ * D + (size_t)row0 * D;
#pragma unroll
        for (int mt = 0; mt < 2; mt++) {
            const int r0 = wm * 32 + mt * 16 + g;
            const float f0 = ssum[r0], f1 = ssum[r0 + 8];
#pragma unroll
            for (int nt = 0; nt < 4; nt++) {
                const int cc = wn * 32 + nt * 8 + 2 * t4;
                *(float2*)&ob[r0 * D + cc] =
                    make_float2(acc[mt][nt][0] * f0, acc[mt][nt][1] * f0);
                *(float2*)&ob[(r0 + 8) * D + cc] =
                    make_float2(acc[mt][nt][2] * f1, acc[mt][nt][3] * f1);
            }
        }
    }
}

// ================= launch =================
extern "C" void kernel_launch(void* const* d_in, const int* in_sizes, int n_in,
                              void* d_out, int out_size) {
    const float* q = (const float*)d_in[0];
    const float* k = (const float*)d_in[1];
    const float* v = (const float*)d_in[2];
    float* out = (float*)d_out;
    (void)in_sizes; (void)n_in; (void)out_size;

    static int attr_set = 0;
    if (!attr_set) {
        cudaFuncSetAttribute(out_kernel, cudaFuncAttributeMaxDynamicSharedMemorySize,
                             K3_SMEM);
        attr_set = 1;
    }

    ctx_partial_kernel<<<dim3(BH, SPLITS), 128>>>(k, v);
    reduce_ctx_kernel<<<dim3(BH, 4), 256>>>();
    out_kernel<<<dim3(BH, 8), 256, K3_SMEM>>>(q, out);
}

// round 15
// speedup vs baseline: 1.0619x; 1.0619x over previous
#include <cuda_runtime.h>
#include <cuda_bf16.h>
#include <cstdint>

#define BH 64
#define SEQ 8192
#define D 64
#define SPLITS 16
#define RPS (SEQ / SPLITS)      // 512
#define K1CH 32
#define K1NCH (RPS / K1CH)      // 16
#define PART_STRIDE (D * D + D)

__device__ float g_part[BH * SPLITS * PART_STRIDE];
__device__ float g_ctx[BH * D * D];

__device__ __forceinline__ uint32_t tf32r(float x) {
    uint32_t r;
    asm("cvt.rna.tf32.f32 %0, %1;" : "=r"(r) : "f"(x));
    return r;
}
__device__ __forceinline__ void mma_tf32(float* c, const uint32_t* a,
                                         uint32_t b0, uint32_t b1) {
    asm volatile(
        "mma.sync.aligned.m16n8k8.row.col.f32.tf32.tf32.f32 "
        "{%0,%1,%2,%3}, {%4,%5,%6,%7}, {%8,%9}, {%0,%1,%2,%3};"
        : "+f"(c[0]), "+f"(c[1]), "+f"(c[2]), "+f"(c[3])
        : "r"(a[0]), "r"(a[1]), "r"(a[2]), "r"(a[3]), "r"(b0), "r"(b1));
}
__device__ __forceinline__ uint32_t smem_u32(const void* p) {
    uint32_t a;
    asm("{ .reg .u64 t; cvta.to.shared.u64 t, %1; cvt.u32.u64 %0, t; }"
        : "=r"(a) : "l"(p));
    return a;
}
__device__ __forceinline__ void cpa16(uint32_t dst, const void* src) {
    asm volatile("cp.async.cg.shared.global [%0], [%1], 16;"
                 :: "r"(dst), "l"(src));
}
#define CPA_COMMIT() asm volatile("cp.async.commit_group;" ::: "memory")
#define CPA_WAIT(n) asm volatile("cp.async.wait_group %0;" :: "n"(n) : "memory")

// ============== Kernel 1: partial context  exp(K)^T @ V  (R12 best) =========
// grid (BH, SPLITS), 128 threads = 4 warps (2x2 tiling, warp tile M32xN32).
// Register staging (LDG->regs->exp/cvt->STS), double buffer, 1 barrier/chunk.
__global__ void __launch_bounds__(128) ctx_partial_kernel(
    const float* __restrict__ k, const float* __restrict__ v) {
    __shared__ __align__(16) uint32_t ek[2][K1CH * 72];  // 18 KB
    __shared__ __align__(16) uint32_t vv[2][K1CH * 72];  // 18 KB
    __shared__ float zred[8][64];

    const int head = blockIdx.x, split = blockIdx.y;
    const float* kb = k + (size_t)head * SEQ * D + (size_t)split * RPS * D;
    const float* vb = v + (size_t)head * SEQ * D + (size_t)split * RPS * D;

    const int tid = threadIdx.x;
    const int lane = tid & 31;
    const int wq = tid >> 5;
    const int g = lane >> 2, t4 = lane & 3;
    const int wm = wq & 1, wn = wq >> 1;
    const int sr = tid >> 4;
    const int c4 = (tid & 15) * 4;

    float acc[2][4][4];
#pragma unroll
    for (int i = 0; i < 2; i++)
#pragma unroll
        for (int j = 0; j < 4; j++)
#pragma unroll
            for (int l = 0; l < 4; l++) acc[i][j][l] = 0.0f;
    float zacc[4] = {0.0f, 0.0f, 0.0f, 0.0f};

    float4 kreg[4], vreg[4];

#define K1_LOAD(c)                                                           \
    {                                                                        \
        _Pragma("unroll") for (int s = 0; s < 4; s++) {                      \
            const int r = s * 8 + sr;                                        \
            kreg[s] = *(const float4*)&kb[(size_t)((c) * K1CH + r) * D + c4];\
            vreg[s] = *(const float4*)&vb[(size_t)((c) * K1CH + r) * D + c4];\
        }                                                                    \
    }

#define K1_STAGE(b)                                                          \
    do {                                                                     \
        _Pragma("unroll") for (int s = 0; s < 4; s++) {                      \
            const int r = s * 8 + sr;                                        \
            uint4 eu, vu;                                                    \
            eu.x = tf32r(__expf(kreg[s].x));                                 \
            eu.y = tf32r(__expf(kreg[s].y));                                 \
            eu.z = tf32r(__expf(kreg[s].z));                                 \
            eu.w = tf32r(__expf(kreg[s].w));                                 \
            zacc[0] += __uint_as_float(eu.x);                                \
            zacc[1] += __uint_as_float(eu.y);                                \
            zacc[2] += __uint_as_float(eu.z);                                \
            zacc[3] += __uint_as_float(eu.w);                                \
            vu.x = tf32r(vreg[s].x); vu.y = tf32r(vreg[s].y);                \
            vu.z = tf32r(vreg[s].z); vu.w = tf32r(vreg[s].w);                \
            *(uint4*)&ek[b][r * 72 + c4] = eu;                               \
            *(uint4*)&vv[b][r * 72 + c4] = vu;                               \
        }                                                                    \
    } while (0)

    K1_LOAD(0);
    K1_STAGE(0);
    __syncthreads();

    for (int c = 0; c < K1NCH; c++) {
        const int p = c & 1;
        if (c + 1 < K1NCH) K1_LOAD(c + 1);
#pragma unroll
        for (int ks = 0; ks < 4; ks++) {
            const int n0 = ks * 8;
            const int ra = (n0 + t4) * 72, rb = (n0 + 4 + t4) * 72;
            uint32_t A[2][4];
#pragma unroll
            for (int mt = 0; mt < 2; mt++) {
                const int dd = wm * 32 + mt * 16 + g;
                A[mt][0] = ek[p][ra + dd];
                A[mt][1] = ek[p][ra + dd + 8];
                A[mt][2] = ek[p][rb + dd];
                A[mt][3] = ek[p][rb + dd + 8];
            }
#pragma unroll
            for (int nt = 0; nt < 4; nt++) {
                const int ee = wn * 32 + nt * 8 + g;
                uint32_t b0 = vv[p][ra + ee];
                uint32_t b1 = vv[p][rb + ee];
                mma_tf32(acc[0][nt], A[0], b0, b1);
                mma_tf32(acc[1][nt], A[1], b0, b1);
            }
        }
        if (c + 1 < K1NCH) K1_STAGE(p ^ 1);
        __syncthreads();
    }

    float* np = g_part + (size_t)(head * SPLITS + split) * PART_STRIDE;
#pragma unroll
    for (int mt = 0; mt < 2; mt++) {
        const int d0 = wm * 32 + mt * 16 + g;
#pragma unroll
        for (int nt = 0; nt < 4; nt++) {
            const int ee = wn * 32 + nt * 8 + 2 * t4;
            *(float2*)&np[d0 * D + ee] =
                make_float2(acc[mt][nt][0], acc[mt][nt][1]);
            *(float2*)&np[(d0 + 8) * D + ee] =
                make_float2(acc[mt][nt][2], acc[mt][nt][3]);
        }
    }
#pragma unroll
    for (int j = 0; j < 4; j++) zred[sr][c4 + j] = zacc[j];
    __syncthreads();
    if (tid < 64) {
        float s = 0.0f;
#pragma unroll
        for (int t = 0; t < 8; t++) s += zred[t][tid];
        np[D * D + tid] = s;
    }
}

// ============== Kernel 2: reduce splits + normalize -> g_ctx ================
__global__ void __launch_bounds__(256) reduce_ctx_kernel() {
    const int head = blockIdx.x;
    const int tid = threadIdx.x;
    __shared__ float zs[D];
    const float* pb = g_part + (size_t)head * SPLITS * PART_STRIDE;

    if (tid < D) {
        float s = 0.0f;
#pragma unroll
        for (int sp = 0; sp < SPLITS; sp++) s += pb[sp * PART_STRIDE + D * D + tid];
        zs[tid] = 1.0f / s;
    }
    __syncthreads();

    const int i0 = blockIdx.y * 1024;
    for (int i = i0 + tid; i < i0 + 1024; i += 256) {
        float s = 0.0f;
#pragma unroll
        for (int sp = 0; sp < SPLITS; sp++) s += pb[sp * PART_STRIDE + i];
        g_ctx[head * D * D + i] = s * zs[i >> 6];
    }
}

// ============== Kernel 3: out = (softmax_ch(q)/8) @ ctx =====================
// grid (BH, 32), 128 threads, 4 tiles of 64 rows (finer grid -> less tail).
// cp.async raw-q depth-2 ring; exp+tf32 at fragment time; row sums from
// A fragments. (R12 structure, K3_TILES 8 -> 4.)
#define K3_TILES 4
#define QS_W 68
#define QS_WORDS (64 * QS_W)                  // 4352
#define K3_SMEM ((2 * QS_WORDS + 64 * 72 + 64) * 4)   // ~53.5 KB

__global__ void __launch_bounds__(128) out_kernel(
    const float* __restrict__ q, float* __restrict__ out) {
    extern __shared__ uint32_t sm3[];
    uint32_t* qs0 = sm3;
    uint32_t* qs1 = sm3 + QS_WORDS;
    uint32_t* ctxs = sm3 + 2 * QS_WORDS;      // 64*72
    float* ssum = (float*)(sm3 + 2 * QS_WORDS + 64 * 72);

    const int tid = threadIdx.x;
    const int lane = tid & 31;
    const int wq = tid >> 5;
    const int g = lane >> 2, t4 = lane & 3;
    const int wm = wq & 1, wn = wq >> 1;
    const int sr = tid >> 4;
    const int c4 = (tid & 15) * 4;
    const int head = blockIdx.x;

    const uint32_t uQs0 = smem_u32(qs0), uQs1 = smem_u32(qs1);

    // stage B = ctx (tf32-rounded), [d][e] rows, stride 72
    const float* gc = g_ctx + (size_t)head * D * D;
    for (int i = tid; i < 64 * 16; i += 128) {
        const int d = i >> 4, cg4 = (i & 15) * 4;
        float4 cv = *(const float4*)&gc[d * D + cg4];
        uint4 cu;
        cu.x = tf32r(cv.x); cu.y = tf32r(cv.y);
        cu.z = tf32r(cv.z); cu.w = tf32r(cv.w);
        *(uint4*)&ctxs[d * 72 + cg4] = cu;
    }

    const float* qh = q + (size_t)head * SEQ * D;
    const int tile0 = blockIdx.y * K3_TILES;

    // prologue: tile 0 -> qs0
#pragma unroll
    for (int s = 0; s < 8; s++) {
        const int r = s * 8 + sr;
        cpa16(uQs0 + (r * QS_W + c4) * 4,
              &qh[(size_t)(tile0 * 64 + r) * D + c4]);
    }
    CPA_COMMIT();

    for (int t = 0; t < K3_TILES; t++) {
        const int p = t & 1;
        const int row0 = (tile0 + t) * 64;

        if (t + 1 < K3_TILES) {
            const uint32_t uDst = p ? uQs0 : uQs1;
#pragma unroll
            for (int s = 0; s < 8; s++) {
                const int r = s * 8 + sr;
                cpa16(uDst + (r * QS_W + c4) * 4,
                      &qh[(size_t)(row0 + 64 + r) * D + c4]);
            }
            CPA_COMMIT();
            CPA_WAIT(1);
        } else {
            CPA_WAIT(0);
        }
        __syncthreads();   // tile t visible

        const uint32_t* qsp = p ? qs1 : qs0;

        float acc[2][4][4];
#pragma unroll
        for (int i = 0; i < 2; i++)
#pragma unroll
            for (int j = 0; j < 4; j++)
#pragma unroll
                for (int l = 0; l < 4; l++) acc[i][j][l] = 0.0f;
        float asum[2][2] = {{0.0f, 0.0f}, {0.0f, 0.0f}};

#pragma unroll
        for (int ks = 0; ks < 8; ks++) {
            const int d0 = ks * 8;
            uint32_t A[2][4];
#pragma unroll
            for (int mt = 0; mt < 2; mt++) {
                const int rb = wm * 32 + mt * 16;
                const float x0 = __uint_as_float(qsp[(rb + g) * QS_W + d0 + t4]);
                const float x1 = __uint_as_float(qsp[(rb + 8 + g) * QS_W + d0 + t4]);
                const float x2 = __uint_as_float(qsp[(rb + g) * QS_W + d0 + 4 + t4]);
                const float x3 = __uint_as_float(qsp[(rb + 8 + g) * QS_W + d0 + 4 + t4]);
                A[mt][0] = tf32r(__expf(x0));
                A[mt][1] = tf32r(__expf(x1));
                A[mt][2] = tf32r(__expf(x2));
                A[mt][3] = tf32r(__expf(x3));
                asum[mt][0] += __uint_as_float(A[mt][0]) + __uint_as_float(A[mt][2]);
                asum[mt][1] += __uint_as_float(A[mt][1]) + __uint_as_float(A[mt][3]);
            }
            const int ra = (d0 + t4) * 72, rbb = (d0 + 4 + t4) * 72;
#pragma unroll
            for (int nt = 0; nt < 4; nt++) {
                const int ee = wn * 32 + nt * 8 + g;
                uint32_t b0 = ctxs[ra + ee];
                uint32_t b1 = ctxs[rbb + ee];
                mma_tf32(acc[0][nt], A[0], b0, b1);
                mma_tf32(acc[1][nt], A[1], b0, b1);
            }
        }

        // complete row sums over t4 lanes; wn==0 publishes
#pragma unroll
        for (int mt = 0; mt < 2; mt++)
#pragma unroll
            for (int h = 0; h < 2; h++) {
                float v = asum[mt][h];
                v += __shfl_xor_sync(0xffffffffu, v, 1);
                v += __shfl_xor_sync(0xffffffffu, v, 2);
                asum[mt][h] = v;
            }
        if (wn == 0 && t4 == 0) {
#pragma unroll
            for (int mt = 0; mt < 2; mt++) {
                const int rb = wm * 32 + mt * 16;
                ssum[rb + g] = 0.125f / asum[mt][0];
                ssum[rb + 8 + g] = 0.125f / asum[mt][1];
            }
        }
        __syncthreads();   // ssum ready; qs[p] reads complete

        float* ob = out + (size_t)head * SEQ * D + (size_t)row0 * D;
#pragma unroll
        for (int mt = 0; mt < 2; mt++) {
            const int r0 = wm * 32 + mt * 16 + g;
            const float f0 = ssum[r0], f1 = ssum[r0 + 8];
#pragma unroll
            for (int nt = 0; nt < 4; nt++) {
                const int cc = wn * 32 + nt * 8 + 2 * t4;
                *(float2*)&ob[r0 * D + cc] =
                    make_float2(acc[mt][nt][0] * f0, acc[mt][nt][1] * f0);
                *(float2*)&ob[(r0 + 8) * D + cc] =
                    make_float2(acc[mt][nt][2] * f1, acc[mt][nt][3] * f1);
            }
        }
    }
}

// ================= launch =================
extern "C" void kernel_launch(void* const* d_in, const int* in_sizes, int n_in,
                              void* d_out, int out_size) {
    const float* q = (const float*)d_in[0];
    const float* k = (const float*)d_in[1];
    const float* v = (const float*)d_in[2];
    float* out = (float*)d_out;
    (void)in_sizes; (void)n_in; (void)out_size;

    static int attr_set = 0;
    if (!attr_set) {
        cudaFuncSetAttribute(out_kernel, cudaFuncAttributeMaxDynamicSharedMemorySize,
                             K3_SMEM);
        attr_set = 1;
    }

    ctx_partial_kernel<<<dim3(BH, SPLITS), 128>>>(k, v);
    reduce_ctx_kernel<<<dim3(BH, 4), 256>>>();
    out_kernel<<<dim3(BH, SEQ / 64 / K3_TILES), 128, K3_SMEM>>>(q, out);
}

// round 17
// speedup vs baseline: 1.0981x; 1.0341x over previous
#include <cuda_runtime.h>
#include <cuda_bf16.h>
#include <cstdint>

#define BH 64
#define SEQ 8192
#define D 64
#define SPLITS 16
#define RPS (SEQ / SPLITS)      // 512
#define K1CH 32
#define K1NCH (RPS / K1CH)      // 16
#define PART_STRIDE (D * D + D)

__device__ float g_part[BH * SPLITS * PART_STRIDE];
__device__ float g_ctx[BH * D * D];

__device__ __forceinline__ uint32_t tf32r(float x) {
    uint32_t r;
    asm("cvt.rna.tf32.f32 %0, %1;" : "=r"(r) : "f"(x));
    return r;
}
__device__ __forceinline__ void mma_tf32(float* c, const uint32_t* a,
                                         uint32_t b0, uint32_t b1) {
    asm volatile(
        "mma.sync.aligned.m16n8k8.row.col.f32.tf32.tf32.f32 "
        "{%0,%1,%2,%3}, {%4,%5,%6,%7}, {%8,%9}, {%0,%1,%2,%3};"
        : "+f"(c[0]), "+f"(c[1]), "+f"(c[2]), "+f"(c[3])
        : "r"(a[0]), "r"(a[1]), "r"(a[2]), "r"(a[3]), "r"(b0), "r"(b1));
}
__device__ __forceinline__ uint32_t smem_u32(const void* p) {
    uint32_t a;
    asm("{ .reg .u64 t; cvta.to.shared.u64 t, %1; cvt.u32.u64 %0, t; }"
        : "=r"(a) : "l"(p));
    return a;
}
__device__ __forceinline__ void cpa16(uint32_t dst, const void* src) {
    asm volatile("cp.async.cg.shared.global [%0], [%1], 16;"
                 :: "r"(dst), "l"(src));
}
#define CPA_COMMIT() asm volatile("cp.async.commit_group;" ::: "memory")
#define CPA_WAIT(n) asm volatile("cp.async.wait_group %0;" :: "n"(n) : "memory")

// ============== Kernel 1: partial context  exp(K)^T @ V  (R12 best, frozen) =
__global__ void __launch_bounds__(128) ctx_partial_kernel(
    const float* __restrict__ k, const float* __restrict__ v) {
    __shared__ __align__(16) uint32_t ek[2][K1CH * 72];  // 18 KB
    __shared__ __align__(16) uint32_t vv[2][K1CH * 72];  // 18 KB
    __shared__ float zred[8][64];

    const int head = blockIdx.x, split = blockIdx.y;
    const float* kb = k + (size_t)head * SEQ * D + (size_t)split * RPS * D;
    const float* vb = v + (size_t)head * SEQ * D + (size_t)split * RPS * D;

    const int tid = threadIdx.x;
    const int lane = tid & 31;
    const int wq = tid >> 5;
    const int g = lane >> 2, t4 = lane & 3;
    const int wm = wq & 1, wn = wq >> 1;
    const int sr = tid >> 4;
    const int c4 = (tid & 15) * 4;

    float acc[2][4][4];
#pragma unroll
    for (int i = 0; i < 2; i++)
#pragma unroll
        for (int j = 0; j < 4; j++)
#pragma unroll
            for (int l = 0; l < 4; l++) acc[i][j][l] = 0.0f;
    float zacc[4] = {0.0f, 0.0f, 0.0f, 0.0f};

    float4 kreg[4], vreg[4];

#define K1_LOAD(c)                                                           \
    {                                                                        \
        _Pragma("unroll") for (int s = 0; s < 4; s++) {                      \
            const int r = s * 8 + sr;                                        \
            kreg[s] = *(const float4*)&kb[(size_t)((c) * K1CH + r) * D + c4];\
            vreg[s] = *(const float4*)&vb[(size_t)((c) * K1CH + r) * D + c4];\
        }                                                                    \
    }

#define K1_STAGE(b)                                                          \
    do {                                                                     \
        _Pragma("unroll") for (int s = 0; s < 4; s++) {                      \
            const int r = s * 8 + sr;                                        \
            uint4 eu, vu;                                                    \
            eu.x = tf32r(__expf(kreg[s].x));                                 \
            eu.y = tf32r(__expf(kreg[s].y));                                 \
            eu.z = tf32r(__expf(kreg[s].z));                                 \
            eu.w = tf32r(__expf(kreg[s].w));                                 \
            zacc[0] += __uint_as_float(eu.x);                                \
            zacc[1] += __uint_as_float(eu.y);                                \
            zacc[2] += __uint_as_float(eu.z);                                \
            zacc[3] += __uint_as_float(eu.w);                                \
            vu.x = tf32r(vreg[s].x); vu.y = tf32r(vreg[s].y);                \
            vu.z = tf32r(vreg[s].z); vu.w = tf32r(vreg[s].w);                \
            *(uint4*)&ek[b][r * 72 + c4] = eu;                               \
            *(uint4*)&vv[b][r * 72 + c4] = vu;                               \
        }                                                                    \
    } while (0)

    K1_LOAD(0);
    K1_STAGE(0);
    __syncthreads();

    for (int c = 0; c < K1NCH; c++) {
        const int p = c & 1;
        if (c + 1 < K1NCH) K1_LOAD(c + 1);
#pragma unroll
        for (int ks = 0; ks < 4; ks++) {
            const int n0 = ks * 8;
            const int ra = (n0 + t4) * 72, rb = (n0 + 4 + t4) * 72;
            uint32_t A[2][4];
#pragma unroll
            for (int mt = 0; mt < 2; mt++) {
                const int dd = wm * 32 + mt * 16 + g;
                A[mt][0] = ek[p][ra + dd];
                A[mt][1] = ek[p][ra + dd + 8];
                A[mt][2] = ek[p][rb + dd];
                A[mt][3] = ek[p][rb + dd + 8];
            }
#pragma unroll
            for (int nt = 0; nt < 4; nt++) {
                const int ee = wn * 32 + nt * 8 + g;
                uint32_t b0 = vv[p][ra + ee];
                uint32_t b1 = vv[p][rb + ee];
                mma_tf32(acc[0][nt], A[0], b0, b1);
                mma_tf32(acc[1][nt], A[1], b0, b1);
            }
        }
        if (c + 1 < K1NCH) K1_STAGE(p ^ 1);
        __syncthreads();
    }

    float* np = g_part + (size_t)(head * SPLITS + split) * PART_STRIDE;
#pragma unroll
    for (int mt = 0; mt < 2; mt++) {
        const int d0 = wm * 32 + mt * 16 + g;
#pragma unroll
        for (int nt = 0; nt < 4; nt++) {
            const int ee = wn * 32 + nt * 8 + 2 * t4;
            *(float2*)&np[d0 * D + ee] =
                make_float2(acc[mt][nt][0], acc[mt][nt][1]);
            *(float2*)&np[(d0 + 8) * D + ee] =
                make_float2(acc[mt][nt][2], acc[mt][nt][3]);
        }
    }
#pragma unroll
    for (int j = 0; j < 4; j++) zred[sr][c4 + j] = zacc[j];
    __syncthreads();
    if (tid < 64) {
        float s = 0.0f;
#pragma unroll
        for (int t = 0; t < 8; t++) s += zred[t][tid];
        np[D * D + tid] = s;
    }
}

// ============== Kernel 2: reduce splits + normalize -> g_ctx (frozen) =======
__global__ void __launch_bounds__(256) reduce_ctx_kernel() {
    const int head = blockIdx.x;
    const int tid = threadIdx.x;
    __shared__ float zs[D];
    const float* pb = g_part + (size_t)head * SPLITS * PART_STRIDE;

    if (tid < D) {
        float s = 0.0f;
#pragma unroll
        for (int sp = 0; sp < SPLITS; sp++) s += pb[sp * PART_STRIDE + D * D + tid];
        zs[tid] = 1.0f / s;
    }
    __syncthreads();

    const int i0 = blockIdx.y * 1024;
    for (int i = i0 + tid; i < i0 + 1024; i += 256) {
        float s = 0.0f;
#pragma unroll
        for (int sp = 0; sp < SPLITS; sp++) s += pb[sp * PART_STRIDE + i];
        g_ctx[head * D * D + i] = s * zs[i >> 6];
    }
}

// ============== Kernel 3: out = (softmax_ch(q)/8) @ ctx  (perm LDS.64) ======
// grid (BH, 16), 128 threads, 8 tiles of 64 rows. k-slot permutation
// perm: hardware slot t4 <-> logical d = d0+2t4, slot t4+4 <-> d0+2t4+1,
// applied to BOTH A and B (sum over d unchanged).
// A: LDS.64 on raw q, stride 72 floats (8B-addr mod 16 = 4g+t4+const,
//    distinct within each 16-lane phase).
// B: ctx staged as float2 pair-rows ctxp[d/2][e], stride 68 float2
//    (8B-addr mod 16 = 4*t4 + g + const, distinct within each phase).
// Fragment LDS per warp per tile: 128 -> 64 instructions.
#define QS_W 72
#define QS_WORDS (64 * QS_W)                  // 4608
#define CTXP_W2 68                            // float2 stride (>=64, ==4 mod 16)
#define CTXP_WORDS (32 * CTXP_W2 * 2)         // 4352 floats
#define K3_SMEM ((2 * QS_WORDS + CTXP_WORDS + 64) * 4)   // 54528 B

__global__ void __launch_bounds__(128) out_kernel(
    const float* __restrict__ q, float* __restrict__ out) {
    extern __shared__ uint32_t sm3[];
    float* qs0 = (float*)sm3;
    float* qs1 = (float*)(sm3 + QS_WORDS);
    float2* ctxp = (float2*)(sm3 + 2 * QS_WORDS);
    float* ssum = (float*)(sm3 + 2 * QS_WORDS + CTXP_WORDS);

    const int tid = threadIdx.x;
    const int lane = tid & 31;
    const int wq = tid >> 5;
    const int g = lane >> 2, t4 = lane & 3;
    const int wm = wq & 1, wn = wq >> 1;
    const int sr = tid >> 4;
    const int c4 = (tid & 15) * 4;
    const int head = blockIdx.x;

    const uint32_t uQs0 = smem_u32(qs0), uQs1 = smem_u32(qs1);

    // stage B: ctxp[pr][e] = (tf32(ctx[2pr][e]), tf32(ctx[2pr+1][e])),
    // row stride CTXP_W2 float2. One float4 store covers columns e2, e2+1.
    const float* gc = g_ctx + (size_t)head * D * D;
    for (int i = tid; i < 32 * 32; i += 128) {
        const int pr = i >> 5, e2 = (i & 31) * 2;
        float2 r0 = *(const float2*)&gc[(2 * pr) * D + e2];
        float2 r1 = *(const float2*)&gc[(2 * pr + 1) * D + e2];
        float4 pq;
        pq.x = __uint_as_float(tf32r(r0.x));   // (ctx[2pr][e2], ctx[2pr+1][e2])
        pq.y = __uint_as_float(tf32r(r1.x));
        pq.z = __uint_as_float(tf32r(r0.y));   // (ctx[2pr][e2+1], ctx[2pr+1][e2+1])
        pq.w = __uint_as_float(tf32r(r1.y));
        *(float4*)&ctxp[pr * CTXP_W2 + e2] = pq;
    }

    const float* qh = q + (size_t)head * SEQ * D;
    const int tile0 = blockIdx.y * 8;

    // prologue: tile 0 -> qs0 (raw q, stride QS_W)
#pragma unroll
    for (int s = 0; s < 8; s++) {
        const int r = s * 8 + sr;
        cpa16(uQs0 + (r * QS_W + c4) * 4,
              &qh[(size_t)(tile0 * 64 + r) * D + c4]);
    }
    CPA_COMMIT();

    for (int t = 0; t < 8; t++) {
        const int p = t & 1;
        const int row0 = (tile0 + t) * 64;

        if (t + 1 < 8) {
            const uint32_t uDst = p ? uQs0 : uQs1;
#pragma unroll
            for (int s = 0; s < 8; s++) {
                const int r = s * 8 + sr;
                cpa16(uDst + (r * QS_W + c4) * 4,
                      &qh[(size_t)(row0 + 64 + r) * D + c4]);
            }
            CPA_COMMIT();
            CPA_WAIT(1);
        } else {
            CPA_WAIT(0);
        }
        __syncthreads();   // tile t visible

        const float* qsp = p ? qs1 : qs0;

        float acc[2][4][4];
#pragma unroll
        for (int i = 0; i < 2; i++)
#pragma unroll
            for (int j = 0; j < 4; j++)
#pragma unroll
                for (int l = 0; l < 4; l++) acc[i][j][l] = 0.0f;
        float asum[2][2] = {{0.0f, 0.0f}, {0.0f, 0.0f}};

#pragma unroll
        for (int ks = 0; ks < 8; ks++) {
            const int d0 = ks * 8;
            uint32_t A[2][4];
#pragma unroll
            for (int mt = 0; mt < 2; mt++) {
                const int rb = wm * 32 + mt * 16;
                // LDS.64: logical d = d0+2t4, d0+2t4+1 (= slots t4, t4+4)
                float2 p0 = *(const float2*)&qsp[(rb + g) * QS_W + d0 + 2 * t4];
                float2 p1 = *(const float2*)&qsp[(rb + 8 + g) * QS_W + d0 + 2 * t4];
                A[mt][0] = tf32r(__expf(p0.x));
                A[mt][2] = tf32r(__expf(p0.y));
                A[mt][1] = tf32r(__expf(p1.x));
                A[mt][3] = tf32r(__expf(p1.y));
                asum[mt][0] += __uint_as_float(A[mt][0]) + __uint_as_float(A[mt][2]);
                asum[mt][1] += __uint_as_float(A[mt][1]) + __uint_as_float(A[mt][3]);
            }
            const int fpr = (ks * 4 + t4) * CTXP_W2;
#pragma unroll
            for (int nt = 0; nt < 4; nt++) {
                const int ee = wn * 32 + nt * 8 + g;
                // LDS.64: (ctx[d0+2t4][ee], ctx[d0+2t4+1][ee]) = slots t4, t4+4
                float2 bb = ctxp[fpr + ee];
                mma_tf32(acc[0][nt], A[0], __float_as_uint(bb.x), __float_as_uint(bb.y));
                mma_tf32(acc[1][nt], A[1], __float_as_uint(bb.x), __float_as_uint(bb.y));
            }
        }

        // complete row sums over t4 lanes; wn==0 publishes
#pragma unroll
        for (int mt = 0; mt < 2; mt++)
#pragma unroll
            for (int h = 0; h < 2; h++) {
                float v = asum[mt][h];
                v += __shfl_xor_sync(0xffffffffu, v, 1);
                v += __shfl_xor_sync(0xffffffffu, v, 2);
                asum[mt][h] = v;
            }
        if (wn == 0 && t4 == 0) {
#pragma unroll
            for (int mt = 0; mt < 2; mt++) {
                const int rb = wm * 32 + mt * 16;
                ssum[rb + g] = 0.125f / asum[mt][0];
                ssum[rb + 8 + g] = 0.125f / asum[mt][1];
            }
        }
        __syncthreads();   // ssum ready; qs[p] reads complete

        float* ob = out + (size_t)head * SEQ * D + (size_t)row0 * D;
#pragma unroll
        for (int mt = 0; mt < 2; mt++) {
            const int r0 = wm * 32 + mt * 16 + g;
            const float f0 = ssum[r0], f1 = ssum[r0 + 8];
#pragma unroll
            for (int nt = 0; nt < 4; nt++) {
                const int cc = wn * 32 + nt * 8 + 2 * t4;
                *(float2*)&ob[r0 * D + cc] =
                    make_float2(acc[mt][nt][0] * f0, acc[mt][nt][1] * f0);
                *(float2*)&ob[(r0 + 8) * D + cc] =
                    make_float2(acc[mt][nt][2] * f1, acc[mt][nt][3] * f1);
            }
        }
    }
}

// ================= launch =================
extern "C" void kernel_launch(void* const* d_in, const int* in_sizes, int n_in,
                              void* d_out, int out_size) {
    const float* q = (const float*)d_in[0];
    const float* k = (const float*)d_in[1];
    const float* v = (const float*)d_in[2];
    float* out = (float*)d_out;
    (void)in_sizes; (void)n_in; (void)out_size;

    static int attr_set = 0;
    if (!attr_set) {
        cudaFuncSetAttribute(out_kernel, cudaFuncAttributeMaxDynamicSharedMemorySize,
                             K3_SMEM);
        attr_set = 1;
    }

    ctx_partial_kernel<<<dim3(BH, SPLITS), 128>>>(k, v);
    reduce_ctx_kernel<<<dim3(BH, 4), 256>>>();
    out_kernel<<<dim3(BH, 16), 128, K3_SMEM>>>(q, out);
}